// round 1
// baseline (speedup 1.0000x reference)
#include <cuda_runtime.h>
#include <cuda_bf16.h>
#include <math.h>

#define B_    4
#define T_    2048
#define C_    1024
#define E_    8
#define H_    4096
#define NTOK  (B_ * T_)     // 8192

// ---------------- scratch (device globals; no runtime allocation) -----------
__device__ int   g_idx[NTOK];
__device__ float g_prob[NTOK];
__device__ int   g_counts[E_];
__device__ int   g_offsets[E_ + 1];
__device__ int   g_cursor[E_];
__device__ int   g_perm[NTOK];
__device__ float g_h[(size_t)NTOK * H_];   // permuted hidden activations, 134 MB

__device__ __forceinline__ float gelu_exact(float v) {
    return 0.5f * v * (1.0f + erff(v * 0.7071067811865476f));
}

// ---------------- 0. zero per-launch counters --------------------------------
__global__ void zero_counts_kernel() {
    if (threadIdx.x < E_) g_counts[threadIdx.x] = 0;
}

// ---------------- 1. router: one warp per token ------------------------------
__global__ __launch_bounds__(256) void router_kernel(
        const float* __restrict__ x, const float* __restrict__ Wr,
        const float* __restrict__ br) {
    int warp = (blockIdx.x * blockDim.x + threadIdx.x) >> 5;
    int lane = threadIdx.x & 31;
    if (warp >= NTOK) return;
    const float* xr = x + (size_t)warp * C_;

    float acc[E_];
#pragma unroll
    for (int e = 0; e < E_; e++) acc[e] = 0.f;

    for (int k = lane; k < C_; k += 32) {
        float xv = xr[k];
        const float* wrow = Wr + k * E_;
#pragma unroll
        for (int e = 0; e < E_; e++) acc[e] += xv * wrow[e];
    }
#pragma unroll
    for (int e = 0; e < E_; e++) {
#pragma unroll
        for (int off = 16; off > 0; off >>= 1)
            acc[e] += __shfl_xor_sync(0xffffffffu, acc[e], off);
    }
    if (lane == 0) {
        float lmax = -1e30f; int best = 0;
#pragma unroll
        for (int e = 0; e < E_; e++) {
            float l = acc[e] + br[e];
            acc[e] = l;
            if (l > lmax) { lmax = l; best = e; }   // first-max tiebreak = argmax
        }
        float s = 0.f;
#pragma unroll
        for (int e = 0; e < E_; e++) s += expf(acc[e] - lmax);
        g_prob[warp] = 1.0f / s;     // max softmax gate = exp(0)/sum
        g_idx[warp]  = best;
        atomicAdd(&g_counts[best], 1);
    }
}

// ---------------- 2. offsets + aux loss (single thread) ----------------------
__global__ void offsets_kernel(float* aux_out) {
    int off = 0;
    float aux = 0.f;
#pragma unroll
    for (int e = 0; e < E_; e++) {
        g_offsets[e] = off;
        g_cursor[e]  = off;
        int c = g_counts[e];
        off += c;
        float frac = (float)c / (float)NTOK;
        float d = frac - (1.0f / (float)E_);
        aux += d * d;
    }
    g_offsets[E_] = off;
    if (aux_out) *aux_out = aux / (float)E_;
}

// ---------------- 3. bucket tokens by expert ---------------------------------
__global__ void permute_kernel() {
    int t = blockIdx.x * blockDim.x + threadIdx.x;
    if (t >= NTOK) return;
    int e = g_idx[t];
    int pos = atomicAdd(&g_cursor[e], 1);
    g_perm[pos] = t;
}

// ---------------- grouped GEMM tiles -----------------------------------------
#define BM 128
#define BN 128
#define BK 16

// GEMM1: h[p, n] = gelu( x[perm[p], :] @ W1[e] + b1[e] ), rows grouped by expert
__global__ __launch_bounds__(256, 2) void gemm1_kernel(
        const float* __restrict__ x, const float* __restrict__ W1,
        const float* __restrict__ b1) {
    int e = blockIdx.z;
    int row_start = g_offsets[e];
    int row_end   = g_offsets[e + 1];
    int r0 = row_start + blockIdx.x * BM;
    if (r0 >= row_end) return;
    int n0 = blockIdx.y * BN;
    const float* W = W1 + (size_t)e * C_ * H_;

    __shared__ float As[BK][BM];
    __shared__ float Bs[BK][BN];

    int tid = threadIdx.x;

    // A-tile loader mapping: 128 rows x 16 cols, 2 float4 per thread
    int arow = tid >> 1;              // 0..127
    int acol = (tid & 1) * 8;         // 0 or 8
    int p    = r0 + arow;
    bool avalid = (p < row_end);
    int tok = avalid ? g_perm[p] : 0;
    const float* arowp = x + (size_t)tok * C_;

    // B-tile loader mapping: 16 rows x 128 cols, 2 float4 per thread
    int brow = tid >> 4;              // 0..15
    int bcol = (tid & 15) * 8;

    // compute mapping: 16x16 threads, each 8x8 outputs
    int tm = (tid >> 4) * 8;
    int tn = (tid & 15) * 8;

    float acc[8][8];
#pragma unroll
    for (int i = 0; i < 8; i++)
#pragma unroll
        for (int j = 0; j < 8; j++) acc[i][j] = 0.f;

    for (int k0 = 0; k0 < C_; k0 += BK) {
        float4 a0, a1;
        if (avalid) {
            a0 = *(const float4*)(arowp + k0 + acol);
            a1 = *(const float4*)(arowp + k0 + acol + 4);
        } else {
            a0 = make_float4(0.f, 0.f, 0.f, 0.f);
            a1 = a0;
        }
        As[acol + 0][arow] = a0.x; As[acol + 1][arow] = a0.y;
        As[acol + 2][arow] = a0.z; As[acol + 3][arow] = a0.w;
        As[acol + 4][arow] = a1.x; As[acol + 5][arow] = a1.y;
        As[acol + 6][arow] = a1.z; As[acol + 7][arow] = a1.w;

        const float* bp = W + (size_t)(k0 + brow) * H_ + n0 + bcol;
        *(float4*)&Bs[brow][bcol]     = *(const float4*)(bp);
        *(float4*)&Bs[brow][bcol + 4] = *(const float4*)(bp + 4);
        __syncthreads();

#pragma unroll
        for (int k = 0; k < BK; k++) {
            float ra[8], rb[8];
            *(float4*)&ra[0] = *(float4*)&As[k][tm];
            *(float4*)&ra[4] = *(float4*)&As[k][tm + 4];
            *(float4*)&rb[0] = *(float4*)&Bs[k][tn];
            *(float4*)&rb[4] = *(float4*)&Bs[k][tn + 4];
#pragma unroll
            for (int i = 0; i < 8; i++)
#pragma unroll
                for (int j = 0; j < 8; j++) acc[i][j] += ra[i] * rb[j];
        }
        __syncthreads();
    }

    float bb[8];
#pragma unroll
    for (int j = 0; j < 8; j++) bb[j] = b1[(size_t)e * H_ + n0 + tn + j];

#pragma unroll
    for (int i = 0; i < 8; i++) {
        int p2 = r0 + tm + i;
        if (p2 >= row_end) break;
        float* hp = g_h + (size_t)p2 * H_ + n0 + tn;
        float4 o0, o1;
        o0.x = gelu_exact(acc[i][0] + bb[0]);
        o0.y = gelu_exact(acc[i][1] + bb[1]);
        o0.z = gelu_exact(acc[i][2] + bb[2]);
        o0.w = gelu_exact(acc[i][3] + bb[3]);
        o1.x = gelu_exact(acc[i][4] + bb[4]);
        o1.y = gelu_exact(acc[i][5] + bb[5]);
        o1.z = gelu_exact(acc[i][6] + bb[6]);
        o1.w = gelu_exact(acc[i][7] + bb[7]);
        *(float4*)(hp)     = o0;
        *(float4*)(hp + 4) = o1;
    }
}

// GEMM2: out[tok, n] = prob[tok] * ( h[p, :] @ W2[e] + b2[e] )
__global__ __launch_bounds__(256, 2) void gemm2_kernel(
        const float* __restrict__ W2, const float* __restrict__ b2,
        float* __restrict__ out) {
    int e = blockIdx.z;
    int row_start = g_offsets[e];
    int row_end   = g_offsets[e + 1];
    int r0 = row_start + blockIdx.x * BM;
    if (r0 >= row_end) return;
    int n0 = blockIdx.y * BN;
    const float* W = W2 + (size_t)e * H_ * C_;

    __shared__ float As[BK][BM];
    __shared__ float Bs[BK][BN];

    int tid = threadIdx.x;
    int arow = tid >> 1;
    int acol = (tid & 1) * 8;
    int p    = r0 + arow;
    bool avalid = (p < row_end);
    const float* arowp = g_h + (size_t)(avalid ? p : r0) * H_;

    int brow = tid >> 4;
    int bcol = (tid & 15) * 8;

    int tm = (tid >> 4) * 8;
    int tn = (tid & 15) * 8;

    float acc[8][8];
#pragma unroll
    for (int i = 0; i < 8; i++)
#pragma unroll
        for (int j = 0; j < 8; j++) acc[i][j] = 0.f;

    for (int k0 = 0; k0 < H_; k0 += BK) {
        float4 a0, a1;
        if (avalid) {
            a0 = *(const float4*)(arowp + k0 + acol);
            a1 = *(const float4*)(arowp + k0 + acol + 4);
        } else {
            a0 = make_float4(0.f, 0.f, 0.f, 0.f);
            a1 = a0;
        }
        As[acol + 0][arow] = a0.x; As[acol + 1][arow] = a0.y;
        As[acol + 2][arow] = a0.z; As[acol + 3][arow] = a0.w;
        As[acol + 4][arow] = a1.x; As[acol + 5][arow] = a1.y;
        As[acol + 6][arow] = a1.z; As[acol + 7][arow] = a1.w;

        const float* bp = W + (size_t)(k0 + brow) * C_ + n0 + bcol;
        *(float4*)&Bs[brow][bcol]     = *(const float4*)(bp);
        *(float4*)&Bs[brow][bcol + 4] = *(const float4*)(bp + 4);
        __syncthreads();

#pragma unroll
        for (int k = 0; k < BK; k++) {
            float ra[8], rb[8];
            *(float4*)&ra[0] = *(float4*)&As[k][tm];
            *(float4*)&ra[4] = *(float4*)&As[k][tm + 4];
            *(float4*)&rb[0] = *(float4*)&Bs[k][tn];
            *(float4*)&rb[4] = *(float4*)&Bs[k][tn + 4];
#pragma unroll
            for (int i = 0; i < 8; i++)
#pragma unroll
                for (int j = 0; j < 8; j++) acc[i][j] += ra[i] * rb[j];
        }
        __syncthreads();
    }

    float bb[8];
#pragma unroll
    for (int j = 0; j < 8; j++) bb[j] = b2[(size_t)e * C_ + n0 + tn + j];

#pragma unroll
    for (int i = 0; i < 8; i++) {
        int p2 = r0 + tm + i;
        if (p2 >= row_end) break;
        int tok = g_perm[p2];
        float g = g_prob[tok];
        float* op = out + (size_t)tok * C_ + n0 + tn;
        float4 o0, o1;
        o0.x = g * (acc[i][0] + bb[0]);
        o0.y = g * (acc[i][1] + bb[1]);
        o0.z = g * (acc[i][2] + bb[2]);
        o0.w = g * (acc[i][3] + bb[3]);
        o1.x = g * (acc[i][4] + bb[4]);
        o1.y = g * (acc[i][5] + bb[5]);
        o1.z = g * (acc[i][6] + bb[6]);
        o1.w = g * (acc[i][7] + bb[7]);
        *(float4*)(op)     = o0;
        *(float4*)(op + 4) = o1;
    }
}

// ---------------- launch ------------------------------------------------------
extern "C" void kernel_launch(void* const* d_in, const int* in_sizes, int n_in,
                              void* d_out, int out_size) {
    const float* x  = (const float*)d_in[0];
    const float* Wr = (const float*)d_in[1];
    const float* br = (const float*)d_in[2];
    const float* W1 = (const float*)d_in[3];
    const float* b1 = (const float*)d_in[4];
    const float* W2 = (const float*)d_in[5];
    const float* b2 = (const float*)d_in[6];
    float* out = (float*)d_out;

    float* aux_ptr = (out_size > NTOK * C_) ? (out + (out_size - 1)) : nullptr;

    zero_counts_kernel<<<1, 32>>>();
    router_kernel<<<NTOK / 8, 256>>>(x, Wr, br);
    offsets_kernel<<<1, 1>>>(aux_ptr);
    permute_kernel<<<NTOK / 256, 256>>>();

    dim3 g1(NTOK / BM, H_ / BN, E_);   // 64 x 32 x 8 (most z-blocks exit early)
    gemm1_kernel<<<g1, 256>>>(x, W1, b1);

    dim3 g2(NTOK / BM, C_ / BN, E_);   // 64 x 8 x 8
    gemm2_kernel<<<g2, 256>>>(W2, b2, out);
}

// round 4
// speedup vs baseline: 2.8767x; 2.8767x over previous
#include <cuda_runtime.h>
#include <cuda_bf16.h>
#include <math.h>
#include <stdint.h>

#define B_    4
#define T_    2048
#define C_    1024
#define E_    8
#define H_    4096
#define NTOK  (B_ * T_)     // 8192

// ---------------- scratch (device globals; no runtime allocation) -----------
__device__ int   g_idx[NTOK];
__device__ float g_prob[NTOK];
__device__ int   g_counts[E_];
__device__ int   g_offsets[E_ + 1];
__device__ int   g_cursor[E_];
__device__ int   g_perm[NTOK];

// split-bf16 operands (hi + lo halves of fp32 values)
__device__ __nv_bfloat16 g_xp_hi[(size_t)NTOK * C_];       // permuted x
__device__ __nv_bfloat16 g_xp_lo[(size_t)NTOK * C_];
__device__ __nv_bfloat16 g_w1t_hi[(size_t)E_ * H_ * C_];   // W1^T  [e][H][C] K-major
__device__ __nv_bfloat16 g_w1t_lo[(size_t)E_ * H_ * C_];
__device__ __nv_bfloat16 g_w2t_hi[(size_t)E_ * C_ * H_];   // W2^T  [e][C][H] K-major
__device__ __nv_bfloat16 g_w2t_lo[(size_t)E_ * C_ * H_];
__device__ __nv_bfloat16 g_h_hi[(size_t)NTOK * H_];        // hidden (permuted rows)
__device__ __nv_bfloat16 g_h_lo[(size_t)NTOK * H_];

__device__ __forceinline__ float gelu_exact(float v) {
    return 0.5f * v * (1.0f + erff(v * 0.7071067811865476f));
}

__device__ __forceinline__ uint32_t smem_u32(const void* p) {
    uint32_t a;
    asm("{ .reg .u64 t; cvta.to.shared.u64 t, %1; cvt.u32.u64 %0, t; }"
        : "=r"(a) : "l"(p));
    return a;
}

#define LDSM4(R0, R1, R2, R3, addr)                                          \
    asm volatile("ldmatrix.sync.aligned.m8n8.x4.shared.b16 {%0,%1,%2,%3}, [%4];" \
                 : "=r"(R0), "=r"(R1), "=r"(R2), "=r"(R3) : "r"(addr))

#define MMA16816(C, A, B0, B1)                                               \
    asm volatile("mma.sync.aligned.m16n8k16.row.col.f32.bf16.bf16.f32 "      \
                 "{%0,%1,%2,%3},{%4,%5,%6,%7},{%8,%9},{%0,%1,%2,%3};"        \
                 : "+f"((C)[0]), "+f"((C)[1]), "+f"((C)[2]), "+f"((C)[3])    \
                 : "r"((A)[0]), "r"((A)[1]), "r"((A)[2]), "r"((A)[3]),       \
                   "r"(B0), "r"(B1))

#define CP_ASYNC16(dst, src)                                                 \
    asm volatile("cp.async.cg.shared.global [%0], [%1], 16;" :: "r"(dst), "l"(src))
#define CP_COMMIT()  asm volatile("cp.async.commit_group;" ::: "memory")
#define CP_WAIT2()   asm volatile("cp.async.wait_group 2;" ::: "memory")
#define CP_WAIT0()   asm volatile("cp.async.wait_group 0;" ::: "memory")

// ---------------- 0-3. routing -----------------------------------------------
__global__ void zero_counts_kernel() {
    if (threadIdx.x < E_) g_counts[threadIdx.x] = 0;
}

__global__ __launch_bounds__(256) void router_kernel(
        const float* __restrict__ x, const float* __restrict__ Wr,
        const float* __restrict__ br) {
    int warp = (blockIdx.x * blockDim.x + threadIdx.x) >> 5;
    int lane = threadIdx.x & 31;
    if (warp >= NTOK) return;
    const float* xr = x + (size_t)warp * C_;
    float acc[E_];
#pragma unroll
    for (int e = 0; e < E_; e++) acc[e] = 0.f;
    for (int k = lane; k < C_; k += 32) {
        float xv = xr[k];
        const float* wrow = Wr + k * E_;
#pragma unroll
        for (int e = 0; e < E_; e++) acc[e] += xv * wrow[e];
    }
#pragma unroll
    for (int e = 0; e < E_; e++) {
#pragma unroll
        for (int off = 16; off > 0; off >>= 1)
            acc[e] += __shfl_xor_sync(0xffffffffu, acc[e], off);
    }
    if (lane == 0) {
        float lmax = -1e30f; int best = 0;
#pragma unroll
        for (int e = 0; e < E_; e++) {
            float l = acc[e] + br[e];
            acc[e] = l;
            if (l > lmax) { lmax = l; best = e; }
        }
        float s = 0.f;
#pragma unroll
        for (int e = 0; e < E_; e++) s += expf(acc[e] - lmax);
        g_prob[warp] = 1.0f / s;
        g_idx[warp]  = best;
        atomicAdd(&g_counts[best], 1);
    }
}

__global__ void offsets_kernel(float* aux_out) {
    int off = 0;
    float aux = 0.f;
#pragma unroll
    for (int e = 0; e < E_; e++) {
        g_offsets[e] = off;
        g_cursor[e]  = off;
        int c = g_counts[e];
        off += c;
        float frac = (float)c / (float)NTOK;
        float d = frac - (1.0f / (float)E_);
        aux += d * d;
    }
    g_offsets[E_] = off;
    if (aux_out) *aux_out = aux / (float)E_;
}

__global__ void permute_kernel() {
    int t = blockIdx.x * blockDim.x + threadIdx.x;
    if (t >= NTOK) return;
    int e = g_idx[t];
    int pos = atomicAdd(&g_cursor[e], 1);
    g_perm[pos] = t;
}

// ---------------- 4. split + permute x into bf16 hi/lo ------------------------
__global__ __launch_bounds__(256) void split_x_kernel(const float* __restrict__ x) {
    int p = blockIdx.x;
    int tok = g_perm[p];
    int k = threadIdx.x * 4;
    float4 v = *(const float4*)(x + (size_t)tok * C_ + k);
    __nv_bfloat16 h0 = __float2bfloat16(v.x);
    __nv_bfloat16 h1 = __float2bfloat16(v.y);
    __nv_bfloat16 h2 = __float2bfloat16(v.z);
    __nv_bfloat16 h3 = __float2bfloat16(v.w);
    __nv_bfloat16 l0 = __float2bfloat16(v.x - __bfloat162float(h0));
    __nv_bfloat16 l1 = __float2bfloat16(v.y - __bfloat162float(h1));
    __nv_bfloat16 l2 = __float2bfloat16(v.z - __bfloat162float(h2));
    __nv_bfloat16 l3 = __float2bfloat16(v.w - __bfloat162float(h3));
    uint2 hw, lw;
    hw.x = ((uint32_t)__bfloat16_as_ushort(h1) << 16) | __bfloat16_as_ushort(h0);
    hw.y = ((uint32_t)__bfloat16_as_ushort(h3) << 16) | __bfloat16_as_ushort(h2);
    lw.x = ((uint32_t)__bfloat16_as_ushort(l1) << 16) | __bfloat16_as_ushort(l0);
    lw.y = ((uint32_t)__bfloat16_as_ushort(l3) << 16) | __bfloat16_as_ushort(l2);
    *(uint2*)(g_xp_hi + (size_t)p * C_ + k) = hw;
    *(uint2*)(g_xp_lo + (size_t)p * C_ + k) = lw;
}

// ---------------- 5. weight transpose + split to K-major bf16 -----------------
template<int WHICH>
__global__ __launch_bounds__(256) void transpose_split_kernel(const float* __restrict__ src) {
    constexpr int R  = (WHICH == 1) ? C_ : H_;
    constexpr int Cc = (WHICH == 1) ? H_ : C_;
    __shared__ float tile[32][33];
    int e = blockIdx.z;
    const float* s = src + (size_t)e * R * Cc;
    __nv_bfloat16* th = ((WHICH == 1) ? g_w1t_hi : g_w2t_hi) + (size_t)e * R * Cc;
    __nv_bfloat16* tl = ((WHICH == 1) ? g_w1t_lo : g_w2t_lo) + (size_t)e * R * Cc;
    int rb = blockIdx.y * 32, cb = blockIdx.x * 32;
    int tx = threadIdx.x, ty = threadIdx.y;
#pragma unroll
    for (int i = 0; i < 4; i++)
        tile[ty + i * 8][tx] = s[(size_t)(rb + ty + i * 8) * Cc + cb + tx];
    __syncthreads();
#pragma unroll
    for (int i = 0; i < 4; i++) {
        float v = tile[tx][ty + i * 8];
        __nv_bfloat16 hi = __float2bfloat16(v);
        __nv_bfloat16 lo = __float2bfloat16(v - __bfloat162float(hi));
        size_t o = (size_t)(cb + ty + i * 8) * R + rb + tx;
        th[o] = hi;
        tl[o] = lo;
    }
}

// ---------------- 6/7. HMMA grouped GEMM (split-bf16, 3 passes folded) -------
// Tiles: BM=128, BN=128, BK=32 bf16. smem row pitch 80B (conflict-free ldmatrix).
// 4-stage cp.async pipeline. K' = 3*KDIM (passes: hi*hi, hi*lo, lo*hi).
#define TILE_B   10240          // 128 rows * 80B
#define STAGE_B  (2 * TILE_B)   // A + B
#define GEMM_SMEM (4 * STAGE_B) // 81920

template<int MODE>
__global__ __launch_bounds__(256) void gemm_hmma_kernel(
        const float* __restrict__ bias, float* __restrict__ out) {
    constexpr int KDIM = (MODE == 1) ? C_ : H_;
    constexpr int NTOT = (MODE == 1) ? H_ : C_;
    constexpr int KCH  = KDIM / 32;       // chunks per pass
    constexpr int NC   = 3 * KCH;         // total chunks

    extern __shared__ char smem[];
    int e = blockIdx.z;
    int row_start = g_offsets[e], row_end = g_offsets[e + 1];
    int r0 = row_start + blockIdx.x * 128;
    if (r0 >= row_end) return;
    int n0 = blockIdx.y * 128;

    int tid  = threadIdx.x;
    int wid  = tid >> 5, lane = tid & 31;
    int wm   = wid & 3;          // warp row  (4 x 32 rows)
    int wn   = wid >> 2;         // warp col  (2 x 64 cols)

    const __nv_bfloat16* Ah = (MODE == 1) ? g_xp_hi : g_h_hi;
    const __nv_bfloat16* Al = (MODE == 1) ? g_xp_lo : g_h_lo;
    const __nv_bfloat16* BhW = ((MODE == 1) ? g_w1t_hi : g_w2t_hi) + (size_t)e * NTOT * KDIM;
    const __nv_bfloat16* BlW = ((MODE == 1) ? g_w1t_lo : g_w2t_lo) + (size_t)e * NTOT * KDIM;

    uint32_t sbase = smem_u32(smem);

    // per-thread copy assignments: 2 A-chunks + 2 B-chunks per stage
    int rowA0 = tid >> 2,          kcA0 = tid & 3;
    int rowA1 = (tid + 256) >> 2,  kcA1 = tid & 3;
    int pA0 = r0 + rowA0; if (pA0 >= row_end) pA0 = row_start;
    int pA1 = r0 + rowA1; if (pA1 >= row_end) pA1 = row_start;
    uint32_t offA0 = rowA0 * 80 + kcA0 * 16;
    uint32_t offA1 = rowA1 * 80 + kcA1 * 16;
    int rowB0 = n0 + rowA0, rowB1 = n0 + rowA1;

    float acc[2][8][4];
#pragma unroll
    for (int i = 0; i < 2; i++)
#pragma unroll
        for (int j = 0; j < 8; j++)
#pragma unroll
            for (int q = 0; q < 4; q++) acc[i][j][q] = 0.f;

    // stage loader
    auto issue = [&](int chunk, int slot) {
        int pass = chunk / KCH;
        int k0   = (chunk - pass * KCH) * 32;
        const __nv_bfloat16* Asrc = (pass < 2) ? Ah : Al;
        const __nv_bfloat16* Bsrc = (pass == 1) ? BlW : BhW;
        uint32_t sA = sbase + slot * STAGE_B;
        uint32_t sB = sA + TILE_B;
        CP_ASYNC16(sA + offA0, Asrc + (size_t)pA0 * KDIM + k0 + kcA0 * 8);
        CP_ASYNC16(sA + offA1, Asrc + (size_t)pA1 * KDIM + k0 + kcA1 * 8);
        CP_ASYNC16(sB + offA0, Bsrc + (size_t)rowB0 * KDIM + k0 + kcA0 * 8);
        CP_ASYNC16(sB + offA1, Bsrc + (size_t)rowB1 * KDIM + k0 + kcA1 * 8);
    };

#pragma unroll
    for (int s = 0; s < 3; s++) { issue(s, s); CP_COMMIT(); }

    // ldmatrix address pieces: row = lane&15, +16B col offset for lanes 16-31
    int lrow = ((lane >> 3) & 1) * 8 + (lane & 7);
    int lkof = ((lane >> 4) & 1) * 8;

    for (int c = 0; c < NC; c++) {
        int slot = c & 3;
        if (c + 3 < NC) { issue(c + 3, (c + 3) & 3); CP_COMMIT(); CP_WAIT2(); }
        else            { CP_WAIT0(); }
        __syncthreads();

        uint32_t sA = sbase + slot * STAGE_B;
        uint32_t sB = sA + TILE_B;

#pragma unroll
        for (int kk = 0; kk < 2; kk++) {
            int k0 = kk * 16;
            uint32_t a[2][4];
#pragma unroll
            for (int mi = 0; mi < 2; mi++) {
                uint32_t addr = sA + (uint32_t)((wm * 32 + mi * 16 + lrow) * 80
                                                + (k0 + lkof) * 2);
                LDSM4(a[mi][0], a[mi][1], a[mi][2], a[mi][3], addr);
            }
            // b[g] regs: 0 = n0-7/k0-7, 1 = n8-15/k0-7, 2 = n0-7/k8-15, 3 = n8-15/k8-15
            uint32_t b[4][4];
#pragma unroll
            for (int g = 0; g < 4; g++) {
                uint32_t addr = sB + (uint32_t)((wn * 64 + g * 16 + lrow) * 80
                                                + (k0 + lkof) * 2);
                LDSM4(b[g][0], b[g][1], b[g][2], b[g][3], addr);
            }
#pragma unroll
            for (int mi = 0; mi < 2; mi++)
#pragma unroll
                for (int ni = 0; ni < 8; ni++) {
                    int gg = ni >> 1, hh = ni & 1;
                    // FIX: pair same-n regs across the two k-halves
                    MMA16816(acc[mi][ni], a[mi], b[gg][hh], b[gg][hh + 2]);
                }
        }
        __syncthreads();
    }

    // ---------------- epilogue ----------------
    int colbase = n0 + wn * 64 + (lane & 3) * 2;
    int rbase   = r0 + wm * 32 + (lane >> 2);
    size_t bofs = (size_t)e * NTOT;

#pragma unroll
    for (int mi = 0; mi < 2; mi++) {
#pragma unroll
        for (int half = 0; half < 2; half++) {       // half 0: rows +0, half 1: rows +8
            int p = rbase + mi * 16 + half * 8;
            if (p >= row_end) continue;
            if (MODE == 1) {
#pragma unroll
                for (int ni = 0; ni < 8; ni++) {
                    int col = colbase + ni * 8;
                    float v0 = acc[mi][ni][half * 2]     + bias[bofs + col];
                    float v1 = acc[mi][ni][half * 2 + 1] + bias[bofs + col + 1];
                    v0 = gelu_exact(v0);
                    v1 = gelu_exact(v1);
                    __nv_bfloat16 h0 = __float2bfloat16(v0);
                    __nv_bfloat16 l0 = __float2bfloat16(v0 - __bfloat162float(h0));
                    __nv_bfloat16 h1 = __float2bfloat16(v1);
                    __nv_bfloat16 l1 = __float2bfloat16(v1 - __bfloat162float(h1));
                    uint32_t hw = ((uint32_t)__bfloat16_as_ushort(h1) << 16)
                                  | __bfloat16_as_ushort(h0);
                    uint32_t lw = ((uint32_t)__bfloat16_as_ushort(l1) << 16)
                                  | __bfloat16_as_ushort(l0);
                    *(uint32_t*)(g_h_hi + (size_t)p * H_ + col) = hw;
                    *(uint32_t*)(g_h_lo + (size_t)p * H_ + col) = lw;
                }
            } else {
                int tok = g_perm[p];
                float gprob = g_prob[tok];
                float* orow = out + (size_t)tok * C_;
#pragma unroll
                for (int ni = 0; ni < 8; ni++) {
                    int col = colbase + ni * 8;
                    float2 o;
                    o.x = gprob * (acc[mi][ni][half * 2]     + bias[bofs + col]);
                    o.y = gprob * (acc[mi][ni][half * 2 + 1] + bias[bofs + col + 1]);
                    *(float2*)(orow + col) = o;
                }
            }
        }
    }
}

// ---------------- launch ------------------------------------------------------
extern "C" void kernel_launch(void* const* d_in, const int* in_sizes, int n_in,
                              void* d_out, int out_size) {
    const float* x  = (const float*)d_in[0];
    const float* Wr = (const float*)d_in[1];
    const float* br = (const float*)d_in[2];
    const float* W1 = (const float*)d_in[3];
    const float* b1 = (const float*)d_in[4];
    const float* W2 = (const float*)d_in[5];
    const float* b2 = (const float*)d_in[6];
    float* out = (float*)d_out;

    float* aux_ptr = (out_size > NTOK * C_) ? (out + (out_size - 1)) : nullptr;

    cudaFuncSetAttribute(gemm_hmma_kernel<1>,
                         cudaFuncAttributeMaxDynamicSharedMemorySize, GEMM_SMEM);
    cudaFuncSetAttribute(gemm_hmma_kernel<2>,
                         cudaFuncAttributeMaxDynamicSharedMemorySize, GEMM_SMEM);

    zero_counts_kernel<<<1, 32>>>();
    router_kernel<<<NTOK / 8, 256>>>(x, Wr, br);
    offsets_kernel<<<1, 1>>>(aux_ptr);
    permute_kernel<<<NTOK / 256, 256>>>();
    split_x_kernel<<<NTOK, 256>>>(x);

    dim3 tb(32, 8);
    transpose_split_kernel<1><<<dim3(H_ / 32, C_ / 32, E_), tb>>>(W1);
    transpose_split_kernel<2><<<dim3(C_ / 32, H_ / 32, E_), tb>>>(W2);

    gemm_hmma_kernel<1><<<dim3(NTOK / 128, H_ / 128, E_), 256, GEMM_SMEM>>>(b1, nullptr);
    gemm_hmma_kernel<2><<<dim3(NTOK / 128, C_ / 128, E_), 256, GEMM_SMEM>>>(b2, out);
}

// round 5
// speedup vs baseline: 3.0061x; 1.0450x over previous
#include <cuda_runtime.h>
#include <cuda_bf16.h>
#include <math.h>
#include <stdint.h>

#define B_    4
#define T_    2048
#define C_    1024
#define E_    8
#define H_    4096
#define NTOK  (B_ * T_)     // 8192

// ---------------- scratch (device globals; no runtime allocation) -----------
__device__ int   g_idx[NTOK];
__device__ float g_prob[NTOK];
__device__ int   g_counts[E_];
__device__ int   g_offsets[E_ + 1];
__device__ int   g_cursor[E_];
__device__ int   g_perm[NTOK];

// split-bf16 operands (hi + lo halves of fp32 values)
__device__ __nv_bfloat16 g_xp_hi[(size_t)NTOK * C_];       // permuted x
__device__ __nv_bfloat16 g_xp_lo[(size_t)NTOK * C_];
__device__ __nv_bfloat16 g_w1t_hi[(size_t)E_ * H_ * C_];   // W1^T  [e][H][C] K-major
__device__ __nv_bfloat16 g_w1t_lo[(size_t)E_ * H_ * C_];
__device__ __nv_bfloat16 g_w2t_hi[(size_t)E_ * C_ * H_];   // W2^T  [e][C][H] K-major
__device__ __nv_bfloat16 g_w2t_lo[(size_t)E_ * C_ * H_];
__device__ __nv_bfloat16 g_h_hi[(size_t)NTOK * H_];        // hidden (permuted rows)
__device__ __nv_bfloat16 g_h_lo[(size_t)NTOK * H_];

__device__ __forceinline__ float gelu_exact(float v) {
    return 0.5f * v * (1.0f + erff(v * 0.7071067811865476f));
}

__device__ __forceinline__ uint32_t smem_u32(const void* p) {
    uint32_t a;
    asm("{ .reg .u64 t; cvta.to.shared.u64 t, %1; cvt.u32.u64 %0, t; }"
        : "=r"(a) : "l"(p));
    return a;
}

#define LDSM4(R0, R1, R2, R3, addr)                                          \
    asm volatile("ldmatrix.sync.aligned.m8n8.x4.shared.b16 {%0,%1,%2,%3}, [%4];" \
                 : "=r"(R0), "=r"(R1), "=r"(R2), "=r"(R3) : "r"(addr))

#define MMA16816(C, A, B0, B1)                                               \
    asm volatile("mma.sync.aligned.m16n8k16.row.col.f32.bf16.bf16.f32 "      \
                 "{%0,%1,%2,%3},{%4,%5,%6,%7},{%8,%9},{%0,%1,%2,%3};"        \
                 : "+f"((C)[0]), "+f"((C)[1]), "+f"((C)[2]), "+f"((C)[3])    \
                 : "r"((A)[0]), "r"((A)[1]), "r"((A)[2]), "r"((A)[3]),       \
                   "r"(B0), "r"(B1))

#define CP_ASYNC16(dst, src)                                                 \
    asm volatile("cp.async.cg.shared.global [%0], [%1], 16;" :: "r"(dst), "l"(src))
#define CP_COMMIT()  asm volatile("cp.async.commit_group;" ::: "memory")
#define CP_WAIT1()   asm volatile("cp.async.wait_group 1;" ::: "memory")
#define CP_WAIT0()   asm volatile("cp.async.wait_group 0;" ::: "memory")

// ---------------- 0-3. routing -----------------------------------------------
__global__ void zero_counts_kernel() {
    if (threadIdx.x < E_) g_counts[threadIdx.x] = 0;
}

__global__ __launch_bounds__(256) void router_kernel(
        const float* __restrict__ x, const float* __restrict__ Wr,
        const float* __restrict__ br) {
    int warp = (blockIdx.x * blockDim.x + threadIdx.x) >> 5;
    int lane = threadIdx.x & 31;
    if (warp >= NTOK) return;
    const float* xr = x + (size_t)warp * C_;
    float acc[E_];
#pragma unroll
    for (int e = 0; e < E_; e++) acc[e] = 0.f;
    for (int k = lane; k < C_; k += 32) {
        float xv = xr[k];
        const float* wrow = Wr + k * E_;
#pragma unroll
        for (int e = 0; e < E_; e++) acc[e] += xv * wrow[e];
    }
#pragma unroll
    for (int e = 0; e < E_; e++) {
#pragma unroll
        for (int off = 16; off > 0; off >>= 1)
            acc[e] += __shfl_xor_sync(0xffffffffu, acc[e], off);
    }
    if (lane == 0) {
        float lmax = -1e30f; int best = 0;
#pragma unroll
        for (int e = 0; e < E_; e++) {
            float l = acc[e] + br[e];
            acc[e] = l;
            if (l > lmax) { lmax = l; best = e; }
        }
        float s = 0.f;
#pragma unroll
        for (int e = 0; e < E_; e++) s += expf(acc[e] - lmax);
        g_prob[warp] = 1.0f / s;
        g_idx[warp]  = best;
        atomicAdd(&g_counts[best], 1);
    }
}

__global__ void offsets_kernel(float* aux_out) {
    int off = 0;
    float aux = 0.f;
#pragma unroll
    for (int e = 0; e < E_; e++) {
        g_offsets[e] = off;
        g_cursor[e]  = off;
        int c = g_counts[e];
        off += c;
        float frac = (float)c / (float)NTOK;
        float d = frac - (1.0f / (float)E_);
        aux += d * d;
    }
    g_offsets[E_] = off;
    if (aux_out) *aux_out = aux / (float)E_;
}

__global__ void permute_kernel() {
    int t = blockIdx.x * blockDim.x + threadIdx.x;
    if (t >= NTOK) return;
    int e = g_idx[t];
    int pos = atomicAdd(&g_cursor[e], 1);
    g_perm[pos] = t;
}

// ---------------- 4. split + permute x into bf16 hi/lo ------------------------
__global__ __launch_bounds__(256) void split_x_kernel(const float* __restrict__ x) {
    int p = blockIdx.x;
    int tok = g_perm[p];
    int k = threadIdx.x * 4;
    float4 v = *(const float4*)(x + (size_t)tok * C_ + k);
    __nv_bfloat16 h0 = __float2bfloat16(v.x);
    __nv_bfloat16 h1 = __float2bfloat16(v.y);
    __nv_bfloat16 h2 = __float2bfloat16(v.z);
    __nv_bfloat16 h3 = __float2bfloat16(v.w);
    __nv_bfloat16 l0 = __float2bfloat16(v.x - __bfloat162float(h0));
    __nv_bfloat16 l1 = __float2bfloat16(v.y - __bfloat162float(h1));
    __nv_bfloat16 l2 = __float2bfloat16(v.z - __bfloat162float(h2));
    __nv_bfloat16 l3 = __float2bfloat16(v.w - __bfloat162float(h3));
    uint2 hw, lw;
    hw.x = ((uint32_t)__bfloat16_as_ushort(h1) << 16) | __bfloat16_as_ushort(h0);
    hw.y = ((uint32_t)__bfloat16_as_ushort(h3) << 16) | __bfloat16_as_ushort(h2);
    lw.x = ((uint32_t)__bfloat16_as_ushort(l1) << 16) | __bfloat16_as_ushort(l0);
    lw.y = ((uint32_t)__bfloat16_as_ushort(l3) << 16) | __bfloat16_as_ushort(l2);
    *(uint2*)(g_xp_hi + (size_t)p * C_ + k) = hw;
    *(uint2*)(g_xp_lo + (size_t)p * C_ + k) = lw;
}

// ---------------- 5. weight transpose + split to K-major bf16 -----------------
template<int WHICH>
__global__ __launch_bounds__(256) void transpose_split_kernel(const float* __restrict__ src) {
    constexpr int R  = (WHICH == 1) ? C_ : H_;
    constexpr int Cc = (WHICH == 1) ? H_ : C_;
    __shared__ float tile[32][33];
    int e = blockIdx.z;
    const float* s = src + (size_t)e * R * Cc;
    __nv_bfloat16* th = ((WHICH == 1) ? g_w1t_hi : g_w2t_hi) + (size_t)e * R * Cc;
    __nv_bfloat16* tl = ((WHICH == 1) ? g_w1t_lo : g_w2t_lo) + (size_t)e * R * Cc;
    int rb = blockIdx.y * 32, cb = blockIdx.x * 32;
    int tx = threadIdx.x, ty = threadIdx.y;
#pragma unroll
    for (int i = 0; i < 4; i++)
        tile[ty + i * 8][tx] = s[(size_t)(rb + ty + i * 8) * Cc + cb + tx];
    __syncthreads();
#pragma unroll
    for (int i = 0; i < 4; i++) {
        float v = tile[tx][ty + i * 8];
        __nv_bfloat16 hi = __float2bfloat16(v);
        __nv_bfloat16 lo = __float2bfloat16(v - __bfloat162float(hi));
        size_t o = (size_t)(cb + ty + i * 8) * R + rb + tx;
        th[o] = hi;
        tl[o] = lo;
    }
}

// ---------------- 6/7. HMMA grouped GEMM (split-bf16, 3 passes folded) -------
// Tiles: BM=128, BN=128, BK=32 bf16. smem row pitch 80B (conflict-free ldmatrix).
// 3-stage cp.async pipeline, ONE barrier per chunk, 2 CTAs/SM.
#define TILE_B   10240          // 128 rows * 80B
#define STAGE_B  (2 * TILE_B)   // A + B
#define GEMM_SMEM (3 * STAGE_B) // 61440

template<int MODE>
__global__ __launch_bounds__(256, 2) void gemm_hmma_kernel(
        const float* __restrict__ bias, float* __restrict__ out) {
    constexpr int KDIM = (MODE == 1) ? C_ : H_;
    constexpr int NTOT = (MODE == 1) ? H_ : C_;
    constexpr int KCH  = KDIM / 32;       // chunks per pass
    constexpr int NC   = 3 * KCH;         // total chunks

    extern __shared__ char smem[];
    int e = blockIdx.z;
    int row_start = g_offsets[e], row_end = g_offsets[e + 1];
    int r0 = row_start + blockIdx.x * 128;
    if (r0 >= row_end) return;
    int n0 = blockIdx.y * 128;

    int tid  = threadIdx.x;
    int wid  = tid >> 5, lane = tid & 31;
    int wm   = wid & 3;          // warp row  (4 x 32 rows)
    int wn   = wid >> 2;         // warp col  (2 x 64 cols)

    const __nv_bfloat16* Ah = (MODE == 1) ? g_xp_hi : g_h_hi;
    const __nv_bfloat16* Al = (MODE == 1) ? g_xp_lo : g_h_lo;
    const __nv_bfloat16* BhW = ((MODE == 1) ? g_w1t_hi : g_w2t_hi) + (size_t)e * NTOT * KDIM;
    const __nv_bfloat16* BlW = ((MODE == 1) ? g_w1t_lo : g_w2t_lo) + (size_t)e * NTOT * KDIM;

    uint32_t sbase = smem_u32(smem);

    // per-thread copy assignments: 2 A-chunks + 2 B-chunks per stage
    int rowA0 = tid >> 2,          kcA0 = tid & 3;
    int rowA1 = (tid + 256) >> 2,  kcA1 = tid & 3;
    int pA0 = r0 + rowA0; if (pA0 >= row_end) pA0 = row_start;
    int pA1 = r0 + rowA1; if (pA1 >= row_end) pA1 = row_start;
    uint32_t offA0 = rowA0 * 80 + kcA0 * 16;
    uint32_t offA1 = rowA1 * 80 + kcA1 * 16;
    int rowB0 = n0 + rowA0, rowB1 = n0 + rowA1;

    float acc[2][8][4];
#pragma unroll
    for (int i = 0; i < 2; i++)
#pragma unroll
        for (int j = 0; j < 8; j++)
#pragma unroll
            for (int q = 0; q < 4; q++) acc[i][j][q] = 0.f;

    auto issue = [&](int chunk, int slot) {
        int pass = chunk / KCH;
        int k0   = (chunk - pass * KCH) * 32;
        const __nv_bfloat16* Asrc = (pass < 2) ? Ah : Al;
        const __nv_bfloat16* Bsrc = (pass == 1) ? BlW : BhW;
        uint32_t sA = sbase + slot * STAGE_B;
        uint32_t sB = sA + TILE_B;
        CP_ASYNC16(sA + offA0, Asrc + (size_t)pA0 * KDIM + k0 + kcA0 * 8);
        CP_ASYNC16(sA + offA1, Asrc + (size_t)pA1 * KDIM + k0 + kcA1 * 8);
        CP_ASYNC16(sB + offA0, Bsrc + (size_t)rowB0 * KDIM + k0 + kcA0 * 8);
        CP_ASYNC16(sB + offA1, Bsrc + (size_t)rowB1 * KDIM + k0 + kcA1 * 8);
    };

    issue(0, 0); CP_COMMIT();
    issue(1, 1); CP_COMMIT();

    // ldmatrix address pieces: row = lane&15, +16B col offset for lanes 16-31
    int lrow = ((lane >> 3) & 1) * 8 + (lane & 7);
    int lkof = ((lane >> 4) & 1) * 8;

    int slot = 0;
    for (int c = 0; c < NC; c++) {
        // wait for stage c; sync; then refill the slot consumed at c-1
        if (c + 2 < NC) { CP_WAIT1(); }
        else            { CP_WAIT0(); }
        __syncthreads();
        if (c + 2 < NC) {
            int ns = slot + 2; if (ns >= 3) ns -= 3;
            issue(c + 2, ns); CP_COMMIT();
        }

        uint32_t sA = sbase + slot * STAGE_B;
        uint32_t sB = sA + TILE_B;

#pragma unroll
        for (int kk = 0; kk < 2; kk++) {
            int k0 = kk * 16;
            uint32_t a[2][4];
#pragma unroll
            for (int mi = 0; mi < 2; mi++) {
                uint32_t addr = sA + (uint32_t)((wm * 32 + mi * 16 + lrow) * 80
                                                + (k0 + lkof) * 2);
                LDSM4(a[mi][0], a[mi][1], a[mi][2], a[mi][3], addr);
            }
            // b[g] regs: 0 = n0-7/k0-7, 1 = n8-15/k0-7, 2 = n0-7/k8-15, 3 = n8-15/k8-15
            uint32_t b[4][4];
#pragma unroll
            for (int g = 0; g < 4; g++) {
                uint32_t addr = sB + (uint32_t)((wn * 64 + g * 16 + lrow) * 80
                                                + (k0 + lkof) * 2);
                LDSM4(b[g][0], b[g][1], b[g][2], b[g][3], addr);
            }
#pragma unroll
            for (int mi = 0; mi < 2; mi++)
#pragma unroll
                for (int ni = 0; ni < 8; ni++) {
                    int gg = ni >> 1, hh = ni & 1;
                    MMA16816(acc[mi][ni], a[mi], b[gg][hh], b[gg][hh + 2]);
                }
        }
        slot++; if (slot >= 3) slot = 0;
    }

    // ---------------- epilogue ----------------
    int colbase = n0 + wn * 64 + (lane & 3) * 2;
    int rbase   = r0 + wm * 32 + (lane >> 2);
    size_t bofs = (size_t)e * NTOT;

#pragma unroll
    for (int mi = 0; mi < 2; mi++) {
#pragma unroll
        for (int half = 0; half < 2; half++) {       // half 0: rows +0, half 1: rows +8
            int p = rbase + mi * 16 + half * 8;
            if (p >= row_end) continue;
            if (MODE == 1) {
#pragma unroll
                for (int ni = 0; ni < 8; ni++) {
                    int col = colbase + ni * 8;
                    float v0 = acc[mi][ni][half * 2]     + bias[bofs + col];
                    float v1 = acc[mi][ni][half * 2 + 1] + bias[bofs + col + 1];
                    v0 = gelu_exact(v0);
                    v1 = gelu_exact(v1);
                    __nv_bfloat16 h0 = __float2bfloat16(v0);
                    __nv_bfloat16 l0 = __float2bfloat16(v0 - __bfloat162float(h0));
                    __nv_bfloat16 h1 = __float2bfloat16(v1);
                    __nv_bfloat16 l1 = __float2bfloat16(v1 - __bfloat162float(h1));
                    uint32_t hw = ((uint32_t)__bfloat16_as_ushort(h1) << 16)
                                  | __bfloat16_as_ushort(h0);
                    uint32_t lw = ((uint32_t)__bfloat16_as_ushort(l1) << 16)
                                  | __bfloat16_as_ushort(l0);
                    *(uint32_t*)(g_h_hi + (size_t)p * H_ + col) = hw;
                    *(uint32_t*)(g_h_lo + (size_t)p * H_ + col) = lw;
                }
            } else {
                int tok = g_perm[p];
                float gprob = g_prob[tok];
                float* orow = out + (size_t)tok * C_;
#pragma unroll
                for (int ni = 0; ni < 8; ni++) {
                    int col = colbase + ni * 8;
                    float2 o;
                    o.x = gprob * (acc[mi][ni][half * 2]     + bias[bofs + col]);
                    o.y = gprob * (acc[mi][ni][half * 2 + 1] + bias[bofs + col + 1]);
                    *(float2*)(orow + col) = o;
                }
            }
        }
    }
}

// ---------------- launch ------------------------------------------------------
extern "C" void kernel_launch(void* const* d_in, const int* in_sizes, int n_in,
                              void* d_out, int out_size) {
    const float* x  = (const float*)d_in[0];
    const float* Wr = (const float*)d_in[1];
    const float* br = (const float*)d_in[2];
    const float* W1 = (const float*)d_in[3];
    const float* b1 = (const float*)d_in[4];
    const float* W2 = (const float*)d_in[5];
    const float* b2 = (const float*)d_in[6];
    float* out = (float*)d_out;

    float* aux_ptr = (out_size > NTOK * C_) ? (out + (out_size - 1)) : nullptr;

    cudaFuncSetAttribute(gemm_hmma_kernel<1>,
                         cudaFuncAttributeMaxDynamicSharedMemorySize, GEMM_SMEM);
    cudaFuncSetAttribute(gemm_hmma_kernel<2>,
                         cudaFuncAttributeMaxDynamicSharedMemorySize, GEMM_SMEM);

    zero_counts_kernel<<<1, 32>>>();
    router_kernel<<<NTOK / 8, 256>>>(x, Wr, br);
    offsets_kernel<<<1, 1>>>(aux_ptr);
    permute_kernel<<<NTOK / 256, 256>>>();
    split_x_kernel<<<NTOK, 256>>>(x);

    dim3 tb(32, 8);
    transpose_split_kernel<1><<<dim3(H_ / 32, C_ / 32, E_), tb>>>(W1);
    transpose_split_kernel<2><<<dim3(C_ / 32, H_ / 32, E_), tb>>>(W2);

    gemm_hmma_kernel<1><<<dim3(NTOK / 128, H_ / 128, E_), 256, GEMM_SMEM>>>(b1, nullptr);
    gemm_hmma_kernel<2><<<dim3(NTOK / 128, C_ / 128, E_), 256, GEMM_SMEM>>>(b2, out);
}

// round 6
// speedup vs baseline: 4.7280x; 1.5728x over previous
#include <cuda_runtime.h>
#include <cuda_fp16.h>
#include <math.h>
#include <stdint.h>

#define B_    4
#define T_    2048
#define C_    1024
#define E_    8
#define H_    4096
#define NTOK  (B_ * T_)     // 8192

// ---------------- scratch (device globals; no runtime allocation) -----------
__device__ int   g_idx[NTOK];
__device__ float g_prob[NTOK];
__device__ int   g_counts[E_];
__device__ int   g_offsets[E_ + 1];
__device__ int   g_cursor[E_];
__device__ int   g_perm[NTOK];

// fp16 operands: A-side split exactly (hi+lo), B-side (weights) rounded hi only
__device__ __half g_xp_hi[(size_t)NTOK * C_];       // permuted x, hi
__device__ __half g_xp_lo[(size_t)NTOK * C_];       // permuted x, lo
__device__ __half g_w1t_hi[(size_t)E_ * H_ * C_];   // fl16(W1^T) [e][H][C] K-major
__device__ __half g_w2t_hi[(size_t)E_ * C_ * H_];   // fl16(W2^T) [e][C][H] K-major
__device__ __half g_h_hi[(size_t)NTOK * H_];        // hidden hi (permuted rows)
__device__ __half g_h_lo[(size_t)NTOK * H_];        // hidden lo

__device__ __forceinline__ float gelu_exact(float v) {
    return 0.5f * v * (1.0f + erff(v * 0.7071067811865476f));
}

__device__ __forceinline__ uint32_t smem_u32(const void* p) {
    uint32_t a;
    asm("{ .reg .u64 t; cvta.to.shared.u64 t, %1; cvt.u32.u64 %0, t; }"
        : "=r"(a) : "l"(p));
    return a;
}

#define LDSM4(R0, R1, R2, R3, addr)                                          \
    asm volatile("ldmatrix.sync.aligned.m8n8.x4.shared.b16 {%0,%1,%2,%3}, [%4];" \
                 : "=r"(R0), "=r"(R1), "=r"(R2), "=r"(R3) : "r"(addr))

#define MMA16816(C, A, B0, B1)                                               \
    asm volatile("mma.sync.aligned.m16n8k16.row.col.f32.f16.f16.f32 "        \
                 "{%0,%1,%2,%3},{%4,%5,%6,%7},{%8,%9},{%0,%1,%2,%3};"        \
                 : "+f"((C)[0]), "+f"((C)[1]), "+f"((C)[2]), "+f"((C)[3])    \
                 : "r"((A)[0]), "r"((A)[1]), "r"((A)[2]), "r"((A)[3]),       \
                   "r"(B0), "r"(B1))

#define CP_ASYNC16(dst, src)                                                 \
    asm volatile("cp.async.cg.shared.global [%0], [%1], 16;" :: "r"(dst), "l"(src))
#define CP_COMMIT()  asm volatile("cp.async.commit_group;" ::: "memory")
#define CP_WAIT1()   asm volatile("cp.async.wait_group 1;" ::: "memory")
#define CP_WAIT0()   asm volatile("cp.async.wait_group 0;" ::: "memory")

// ---------------- 0-3. routing -----------------------------------------------
__global__ void zero_counts_kernel() {
    if (threadIdx.x < E_) g_counts[threadIdx.x] = 0;
}

__global__ __launch_bounds__(256) void router_kernel(
        const float* __restrict__ x, const float* __restrict__ Wr,
        const float* __restrict__ br) {
    int warp = (blockIdx.x * blockDim.x + threadIdx.x) >> 5;
    int lane = threadIdx.x & 31;
    if (warp >= NTOK) return;
    const float* xr = x + (size_t)warp * C_;
    float acc[E_];
#pragma unroll
    for (int e = 0; e < E_; e++) acc[e] = 0.f;
    for (int k = lane; k < C_; k += 32) {
        float xv = xr[k];
        const float* wrow = Wr + k * E_;
#pragma unroll
        for (int e = 0; e < E_; e++) acc[e] += xv * wrow[e];
    }
#pragma unroll
    for (int e = 0; e < E_; e++) {
#pragma unroll
        for (int off = 16; off > 0; off >>= 1)
            acc[e] += __shfl_xor_sync(0xffffffffu, acc[e], off);
    }
    if (lane == 0) {
        float lmax = -1e30f; int best = 0;
#pragma unroll
        for (int e = 0; e < E_; e++) {
            float l = acc[e] + br[e];
            acc[e] = l;
            if (l > lmax) { lmax = l; best = e; }
        }
        float s = 0.f;
#pragma unroll
        for (int e = 0; e < E_; e++) s += expf(acc[e] - lmax);
        g_prob[warp] = 1.0f / s;
        g_idx[warp]  = best;
        atomicAdd(&g_counts[best], 1);
    }
}

__global__ void offsets_kernel(float* aux_out) {
    int off = 0;
    float aux = 0.f;
#pragma unroll
    for (int e = 0; e < E_; e++) {
        g_offsets[e] = off;
        g_cursor[e]  = off;
        int c = g_counts[e];
        off += c;
        float frac = (float)c / (float)NTOK;
        float d = frac - (1.0f / (float)E_);
        aux += d * d;
    }
    g_offsets[E_] = off;
    if (aux_out) *aux_out = aux / (float)E_;
}

__global__ void permute_kernel() {
    int t = blockIdx.x * blockDim.x + threadIdx.x;
    if (t >= NTOK) return;
    int e = g_idx[t];
    int pos = atomicAdd(&g_cursor[e], 1);
    g_perm[pos] = t;
}

// ---------------- 4. split + permute x into fp16 hi/lo ------------------------
__global__ __launch_bounds__(256) void split_x_kernel(const float* __restrict__ x) {
    int p = blockIdx.x;
    int tok = g_perm[p];
    int k = threadIdx.x * 4;
    float4 v = *(const float4*)(x + (size_t)tok * C_ + k);
    __half h0 = __float2half_rn(v.x);
    __half h1 = __float2half_rn(v.y);
    __half h2 = __float2half_rn(v.z);
    __half h3 = __float2half_rn(v.w);
    __half l0 = __float2half_rn(v.x - __half2float(h0));
    __half l1 = __float2half_rn(v.y - __half2float(h1));
    __half l2 = __float2half_rn(v.z - __half2float(h2));
    __half l3 = __float2half_rn(v.w - __half2float(h3));
    uint2 hw, lw;
    hw.x = ((uint32_t)__half_as_ushort(h1) << 16) | __half_as_ushort(h0);
    hw.y = ((uint32_t)__half_as_ushort(h3) << 16) | __half_as_ushort(h2);
    lw.x = ((uint32_t)__half_as_ushort(l1) << 16) | __half_as_ushort(l0);
    lw.y = ((uint32_t)__half_as_ushort(l3) << 16) | __half_as_ushort(l2);
    *(uint2*)(g_xp_hi + (size_t)p * C_ + k) = hw;
    *(uint2*)(g_xp_lo + (size_t)p * C_ + k) = lw;
}

// ---------------- 5. weight transpose to K-major fp16 (hi only) ---------------
template<int WHICH>
__global__ __launch_bounds__(256) void transpose_split_kernel(const float* __restrict__ src) {
    constexpr int R  = (WHICH == 1) ? C_ : H_;
    constexpr int Cc = (WHICH == 1) ? H_ : C_;
    __shared__ float tile[32][33];
    int e = blockIdx.z;
    const float* s = src + (size_t)e * R * Cc;
    __half* th = ((WHICH == 1) ? g_w1t_hi : g_w2t_hi) + (size_t)e * R * Cc;
    int rb = blockIdx.y * 32, cb = blockIdx.x * 32;
    int tx = threadIdx.x, ty = threadIdx.y;
#pragma unroll
    for (int i = 0; i < 4; i++)
        tile[ty + i * 8][tx] = s[(size_t)(rb + ty + i * 8) * Cc + cb + tx];
    __syncthreads();
#pragma unroll
    for (int i = 0; i < 4; i++) {
        float v = tile[tx][ty + i * 8];
        th[(size_t)(cb + ty + i * 8) * R + rb + tx] = __float2half_rn(v);
    }
}

// ---------------- 6/7. HMMA grouped GEMM (fp16 2-pass: A hi/lo x B hi) --------
// Tiles: BM=128, BN=128, BK=32 fp16. Pitch-80 rows. 3-stage cp.async pipeline.
// Per chunk: B fragments loaded once, reused by both A passes.
#define TILE_B   10240            // 128 rows * 80B
#define STAGE_B  (3 * TILE_B)     // Ahi + Alo + Bhi
#define GEMM_SMEM (3 * STAGE_B)   // 92160

template<int MODE>
__global__ __launch_bounds__(256, 2) void gemm_hmma_kernel(
        const float* __restrict__ bias, float* __restrict__ out) {
    constexpr int KDIM = (MODE == 1) ? C_ : H_;
    constexpr int NTOT = (MODE == 1) ? H_ : C_;
    constexpr int NC   = KDIM / 32;        // chunks

    extern __shared__ char smem[];
    int e = blockIdx.z;
    int row_start = g_offsets[e], row_end = g_offsets[e + 1];
    int r0 = row_start + blockIdx.x * 128;
    if (r0 >= row_end) return;
    int n0 = blockIdx.y * 128;

    int tid  = threadIdx.x;
    int wid  = tid >> 5, lane = tid & 31;
    int wm   = wid & 3;          // warp row  (4 x 32 rows)
    int wn   = wid >> 2;         // warp col  (2 x 64 cols)

    const __half* Ah = (MODE == 1) ? g_xp_hi : g_h_hi;
    const __half* Al = (MODE == 1) ? g_xp_lo : g_h_lo;
    const __half* Bh = ((MODE == 1) ? g_w1t_hi : g_w2t_hi) + (size_t)e * NTOT * KDIM;

    uint32_t sbase = smem_u32(smem);

    // copy mapping: per tile, each thread moves 2x 16B (rows tid>>2 and +64)
    int rowA0 = tid >> 2,  kc = tid & 3;
    int rowA1 = rowA0 + 64;
    int pA0 = r0 + rowA0; if (pA0 >= row_end) pA0 = row_start;
    int pA1 = r0 + rowA1; if (pA1 >= row_end) pA1 = row_start;
    uint32_t off0 = rowA0 * 80 + kc * 16;
    uint32_t off1 = rowA1 * 80 + kc * 16;
    int rowB0 = n0 + rowA0, rowB1 = n0 + rowA1;

    float acc[2][8][4];
#pragma unroll
    for (int i = 0; i < 2; i++)
#pragma unroll
        for (int j = 0; j < 8; j++)
#pragma unroll
            for (int q = 0; q < 4; q++) acc[i][j][q] = 0.f;

    auto issue = [&](int chunk, int slot) {
        int k0 = chunk * 32;
        uint32_t sAh = sbase + slot * STAGE_B;
        uint32_t sAl = sAh + TILE_B;
        uint32_t sB  = sAl + TILE_B;
        CP_ASYNC16(sAh + off0, Ah + (size_t)pA0 * KDIM + k0 + kc * 8);
        CP_ASYNC16(sAh + off1, Ah + (size_t)pA1 * KDIM + k0 + kc * 8);
        CP_ASYNC16(sAl + off0, Al + (size_t)pA0 * KDIM + k0 + kc * 8);
        CP_ASYNC16(sAl + off1, Al + (size_t)pA1 * KDIM + k0 + kc * 8);
        CP_ASYNC16(sB  + off0, Bh + (size_t)rowB0 * KDIM + k0 + kc * 8);
        CP_ASYNC16(sB  + off1, Bh + (size_t)rowB1 * KDIM + k0 + kc * 8);
    };

    issue(0, 0); CP_COMMIT();
    issue(1, 1); CP_COMMIT();

    // ldmatrix lane address pieces
    int lrow = ((lane >> 3) & 1) * 8 + (lane & 7);
    int lkof = ((lane >> 4) & 1) * 8;

    int slot = 0;
    for (int c = 0; c < NC; c++) {
        if (c + 2 < NC) { CP_WAIT1(); }
        else            { CP_WAIT0(); }
        __syncthreads();
        if (c + 2 < NC) {
            int ns = slot + 2; if (ns >= 3) ns -= 3;
            issue(c + 2, ns); CP_COMMIT();
        }

        uint32_t sAh = sbase + slot * STAGE_B;
        uint32_t sAl = sAh + TILE_B;
        uint32_t sB  = sAl + TILE_B;

#pragma unroll
        for (int kk = 0; kk < 2; kk++) {
            int k0 = kk * 16;
            // B fragments once per kk (shared by both A passes)
            // b[g] regs: 0 = n0-7/k0-7, 1 = n8-15/k0-7, 2 = n0-7/k8-15, 3 = n8-15/k8-15
            uint32_t b[4][4];
#pragma unroll
            for (int g = 0; g < 4; g++) {
                uint32_t addr = sB + (uint32_t)((wn * 64 + g * 16 + lrow) * 80
                                                + (k0 + lkof) * 2);
                LDSM4(b[g][0], b[g][1], b[g][2], b[g][3], addr);
            }
            // pass 1: A-hi
            uint32_t a[2][4];
#pragma unroll
            for (int mi = 0; mi < 2; mi++) {
                uint32_t addr = sAh + (uint32_t)((wm * 32 + mi * 16 + lrow) * 80
                                                 + (k0 + lkof) * 2);
                LDSM4(a[mi][0], a[mi][1], a[mi][2], a[mi][3], addr);
            }
#pragma unroll
            for (int mi = 0; mi < 2; mi++)
#pragma unroll
                for (int ni = 0; ni < 8; ni++) {
                    int gg = ni >> 1, hh = ni & 1;
                    MMA16816(acc[mi][ni], a[mi], b[gg][hh], b[gg][hh + 2]);
                }
            // pass 2: A-lo (same B frags)
#pragma unroll
            for (int mi = 0; mi < 2; mi++) {
                uint32_t addr = sAl + (uint32_t)((wm * 32 + mi * 16 + lrow) * 80
                                                 + (k0 + lkof) * 2);
                LDSM4(a[mi][0], a[mi][1], a[mi][2], a[mi][3], addr);
            }
#pragma unroll
            for (int mi = 0; mi < 2; mi++)
#pragma unroll
                for (int ni = 0; ni < 8; ni++) {
                    int gg = ni >> 1, hh = ni & 1;
                    MMA16816(acc[mi][ni], a[mi], b[gg][hh], b[gg][hh + 2]);
                }
        }
        slot++; if (slot >= 3) slot = 0;
    }

    // ---------------- epilogue ----------------
    int colbase = n0 + wn * 64 + (lane & 3) * 2;
    int rbase   = r0 + wm * 32 + (lane >> 2);
    size_t bofs = (size_t)e * NTOT;

#pragma unroll
    for (int mi = 0; mi < 2; mi++) {
#pragma unroll
        for (int half = 0; half < 2; half++) {
            int p = rbase + mi * 16 + half * 8;
            if (p >= row_end) continue;
            if (MODE == 1) {
#pragma unroll
                for (int ni = 0; ni < 8; ni++) {
                    int col = colbase + ni * 8;
                    float v0 = acc[mi][ni][half * 2]     + bias[bofs + col];
                    float v1 = acc[mi][ni][half * 2 + 1] + bias[bofs + col + 1];
                    v0 = gelu_exact(v0);
                    v1 = gelu_exact(v1);
                    __half h0 = __float2half_rn(v0);
                    __half l0 = __float2half_rn(v0 - __half2float(h0));
                    __half h1 = __float2half_rn(v1);
                    __half l1 = __float2half_rn(v1 - __half2float(h1));
                    uint32_t hw = ((uint32_t)__half_as_ushort(h1) << 16)
                                  | __half_as_ushort(h0);
                    uint32_t lw = ((uint32_t)__half_as_ushort(l1) << 16)
                                  | __half_as_ushort(l0);
                    *(uint32_t*)(g_h_hi + (size_t)p * H_ + col) = hw;
                    *(uint32_t*)(g_h_lo + (size_t)p * H_ + col) = lw;
                }
            } else {
                int tok = g_perm[p];
                float gprob = g_prob[tok];
                float* orow = out + (size_t)tok * C_;
#pragma unroll
                for (int ni = 0; ni < 8; ni++) {
                    int col = colbase + ni * 8;
                    float2 o;
                    o.x = gprob * (acc[mi][ni][half * 2]     + bias[bofs + col]);
                    o.y = gprob * (acc[mi][ni][half * 2 + 1] + bias[bofs + col + 1]);
                    *(float2*)(orow + col) = o;
                }
            }
        }
    }
}

// ---------------- launch ------------------------------------------------------
extern "C" void kernel_launch(void* const* d_in, const int* in_sizes, int n_in,
                              void* d_out, int out_size) {
    const float* x  = (const float*)d_in[0];
    const float* Wr = (const float*)d_in[1];
    const float* br = (const float*)d_in[2];
    const float* W1 = (const float*)d_in[3];
    const float* b1 = (const float*)d_in[4];
    const float* W2 = (const float*)d_in[5];
    const float* b2 = (const float*)d_in[6];
    float* out = (float*)d_out;

    float* aux_ptr = (out_size > NTOK * C_) ? (out + (out_size - 1)) : nullptr;

    cudaFuncSetAttribute(gemm_hmma_kernel<1>,
                         cudaFuncAttributeMaxDynamicSharedMemorySize, GEMM_SMEM);
    cudaFuncSetAttribute(gemm_hmma_kernel<2>,
                         cudaFuncAttributeMaxDynamicSharedMemorySize, GEMM_SMEM);

    zero_counts_kernel<<<1, 32>>>();
    router_kernel<<<NTOK / 8, 256>>>(x, Wr, br);
    offsets_kernel<<<1, 1>>>(aux_ptr);
    permute_kernel<<<NTOK / 256, 256>>>();
    split_x_kernel<<<NTOK, 256>>>(x);

    dim3 tb(32, 8);
    transpose_split_kernel<1><<<dim3(H_ / 32, C_ / 32, E_), tb>>>(W1);
    transpose_split_kernel<2><<<dim3(C_ / 32, H_ / 32, E_), tb>>>(W2);

    gemm_hmma_kernel<1><<<dim3(NTOK / 128, H_ / 128, E_), 256, GEMM_SMEM>>>(b1, nullptr);
    gemm_hmma_kernel<2><<<dim3(NTOK / 128, C_ / 128, E_), 256, GEMM_SMEM>>>(b2, out);
}

// round 7
// speedup vs baseline: 7.4263x; 1.5707x over previous
#include <cuda_runtime.h>
#include <cuda_fp16.h>
#include <math.h>
#include <stdint.h>

#define B_    4
#define T_    2048
#define C_    1024
#define E_    8
#define H_    4096
#define NTOK  (B_ * T_)     // 8192

// ---------------- scratch (device globals; no runtime allocation) -----------
__device__ int   g_idx[NTOK];
__device__ float g_prob[NTOK];
__device__ int   g_counts[E_];
__device__ int   g_offsets[E_ + 1];
__device__ int   g_cursor[E_];
__device__ int   g_perm[NTOK];

// fp16 operands (single-rounded; fp32 accumulate in MMA)
__device__ __half g_xp[(size_t)NTOK * C_];        // permuted x
__device__ __half g_w1t[(size_t)E_ * H_ * C_];    // fl16(W1^T) [e][H][C] K-major
__device__ __half g_w2t[(size_t)E_ * C_ * H_];    // fl16(W2^T) [e][C][H] K-major
__device__ __half g_h[(size_t)NTOK * H_];         // hidden (permuted rows)

__device__ __forceinline__ float gelu_exact(float v) {
    return 0.5f * v * (1.0f + erff(v * 0.7071067811865476f));
}

__device__ __forceinline__ uint32_t smem_u32(const void* p) {
    uint32_t a;
    asm("{ .reg .u64 t; cvta.to.shared.u64 t, %1; cvt.u32.u64 %0, t; }"
        : "=r"(a) : "l"(p));
    return a;
}

#define LDSM4(R0, R1, R2, R3, addr)                                          \
    asm volatile("ldmatrix.sync.aligned.m8n8.x4.shared.b16 {%0,%1,%2,%3}, [%4];" \
                 : "=r"(R0), "=r"(R1), "=r"(R2), "=r"(R3) : "r"(addr))

#define MMA16816(C, A, B0, B1)                                               \
    asm volatile("mma.sync.aligned.m16n8k16.row.col.f32.f16.f16.f32 "        \
                 "{%0,%1,%2,%3},{%4,%5,%6,%7},{%8,%9},{%0,%1,%2,%3};"        \
                 : "+f"((C)[0]), "+f"((C)[1]), "+f"((C)[2]), "+f"((C)[3])    \
                 : "r"((A)[0]), "r"((A)[1]), "r"((A)[2]), "r"((A)[3]),       \
                   "r"(B0), "r"(B1))

#define CP_ASYNC16(dst, src)                                                 \
    asm volatile("cp.async.cg.shared.global [%0], [%1], 16;" :: "r"(dst), "l"(src))
#define CP_COMMIT()  asm volatile("cp.async.commit_group;" ::: "memory")
#define CP_WAIT2()   asm volatile("cp.async.wait_group 2;" ::: "memory")
#define CP_WAIT0()   asm volatile("cp.async.wait_group 0;" ::: "memory")

// ---------------- 0-3. routing -----------------------------------------------
__global__ void zero_counts_kernel() {
    if (threadIdx.x < E_) g_counts[threadIdx.x] = 0;
}

__global__ __launch_bounds__(256) void router_kernel(
        const float* __restrict__ x, const float* __restrict__ Wr,
        const float* __restrict__ br) {
    int warp = (blockIdx.x * blockDim.x + threadIdx.x) >> 5;
    int lane = threadIdx.x & 31;
    if (warp >= NTOK) return;
    const float* xr = x + (size_t)warp * C_;
    float acc[E_];
#pragma unroll
    for (int e = 0; e < E_; e++) acc[e] = 0.f;
    for (int k = lane; k < C_; k += 32) {
        float xv = xr[k];
        const float* wrow = Wr + k * E_;
#pragma unroll
        for (int e = 0; e < E_; e++) acc[e] += xv * wrow[e];
    }
#pragma unroll
    for (int e = 0; e < E_; e++) {
#pragma unroll
        for (int off = 16; off > 0; off >>= 1)
            acc[e] += __shfl_xor_sync(0xffffffffu, acc[e], off);
    }
    if (lane == 0) {
        float lmax = -1e30f; int best = 0;
#pragma unroll
        for (int e = 0; e < E_; e++) {
            float l = acc[e] + br[e];
            acc[e] = l;
            if (l > lmax) { lmax = l; best = e; }
        }
        float s = 0.f;
#pragma unroll
        for (int e = 0; e < E_; e++) s += expf(acc[e] - lmax);
        g_prob[warp] = 1.0f / s;
        g_idx[warp]  = best;
        atomicAdd(&g_counts[best], 1);
    }
}

__global__ void offsets_kernel(float* aux_out) {
    int off = 0;
    float aux = 0.f;
#pragma unroll
    for (int e = 0; e < E_; e++) {
        g_offsets[e] = off;
        g_cursor[e]  = off;
        int c = g_counts[e];
        off += c;
        float frac = (float)c / (float)NTOK;
        float d = frac - (1.0f / (float)E_);
        aux += d * d;
    }
    g_offsets[E_] = off;
    if (aux_out) *aux_out = aux / (float)E_;
}

__global__ void permute_kernel() {
    int t = blockIdx.x * blockDim.x + threadIdx.x;
    if (t >= NTOK) return;
    int e = g_idx[t];
    int pos = atomicAdd(&g_cursor[e], 1);
    g_perm[pos] = t;
}

// ---------------- 4. convert + permute x to fp16 ------------------------------
__global__ __launch_bounds__(256) void convert_x_kernel(const float* __restrict__ x) {
    int p = blockIdx.x;
    int tok = g_perm[p];
    int k = threadIdx.x * 4;
    float4 v = *(const float4*)(x + (size_t)tok * C_ + k);
    uint2 hw;
    hw.x = ((uint32_t)__half_as_ushort(__float2half_rn(v.y)) << 16)
           | __half_as_ushort(__float2half_rn(v.x));
    hw.y = ((uint32_t)__half_as_ushort(__float2half_rn(v.w)) << 16)
           | __half_as_ushort(__float2half_rn(v.z));
    *(uint2*)(g_xp + (size_t)p * C_ + k) = hw;
}

// ---------------- 5. weight transpose to K-major fp16 -------------------------
template<int WHICH>
__global__ __launch_bounds__(256) void transpose_kernel(const float* __restrict__ src) {
    constexpr int R  = (WHICH == 1) ? C_ : H_;
    constexpr int Cc = (WHICH == 1) ? H_ : C_;
    __shared__ float tile[32][33];
    int e = blockIdx.z;
    const float* s = src + (size_t)e * R * Cc;
    __half* th = ((WHICH == 1) ? g_w1t : g_w2t) + (size_t)e * R * Cc;
    int rb = blockIdx.y * 32, cb = blockIdx.x * 32;
    int tx = threadIdx.x, ty = threadIdx.y;
#pragma unroll
    for (int i = 0; i < 4; i++)
        tile[ty + i * 8][tx] = s[(size_t)(rb + ty + i * 8) * Cc + cb + tx];
    __syncthreads();
#pragma unroll
    for (int i = 0; i < 4; i++) {
        float v = tile[tx][ty + i * 8];
        th[(size_t)(cb + ty + i * 8) * R + rb + tx] = __float2half_rn(v);
    }
}

// ---------------- 6/7. HMMA grouped GEMM (single-pass fp16) -------------------
// Tiles: BM=128, BN=128, BK=32 fp16. Pitch-80 rows. 4-stage cp.async pipeline.
#define TILE_B   10240            // 128 rows * 80B
#define STAGE_B  (2 * TILE_B)     // A + B
#define GEMM_SMEM (4 * STAGE_B)   // 81920

template<int MODE>
__global__ __launch_bounds__(256, 2) void gemm_hmma_kernel(
        const float* __restrict__ bias, float* __restrict__ out) {
    constexpr int KDIM = (MODE == 1) ? C_ : H_;
    constexpr int NTOT = (MODE == 1) ? H_ : C_;
    constexpr int NC   = KDIM / 32;        // chunks

    extern __shared__ char smem[];
    int e = blockIdx.z;
    int row_start = g_offsets[e], row_end = g_offsets[e + 1];
    int r0 = row_start + blockIdx.x * 128;
    if (r0 >= row_end) return;
    int n0 = blockIdx.y * 128;

    int tid  = threadIdx.x;
    int wid  = tid >> 5, lane = tid & 31;
    int wm   = wid & 3;          // warp row  (4 x 32 rows)
    int wn   = wid >> 2;         // warp col  (2 x 64 cols)

    const __half* A = (MODE == 1) ? g_xp : g_h;
    const __half* Bw = ((MODE == 1) ? g_w1t : g_w2t) + (size_t)e * NTOT * KDIM;

    uint32_t sbase = smem_u32(smem);

    // copy mapping: per tile, each thread moves 2x 16B (rows tid>>2 and +64)
    int rowA0 = tid >> 2,  kc = tid & 3;
    int rowA1 = rowA0 + 64;
    int pA0 = r0 + rowA0; if (pA0 >= row_end) pA0 = row_start;
    int pA1 = r0 + rowA1; if (pA1 >= row_end) pA1 = row_start;
    uint32_t off0 = rowA0 * 80 + kc * 16;
    uint32_t off1 = rowA1 * 80 + kc * 16;
    int rowB0 = n0 + rowA0, rowB1 = n0 + rowA1;

    float acc[2][8][4];
#pragma unroll
    for (int i = 0; i < 2; i++)
#pragma unroll
        for (int j = 0; j < 8; j++)
#pragma unroll
            for (int q = 0; q < 4; q++) acc[i][j][q] = 0.f;

    auto issue = [&](int chunk, int slot) {
        int k0 = chunk * 32;
        uint32_t sA = sbase + slot * STAGE_B;
        uint32_t sB = sA + TILE_B;
        CP_ASYNC16(sA + off0, A + (size_t)pA0 * KDIM + k0 + kc * 8);
        CP_ASYNC16(sA + off1, A + (size_t)pA1 * KDIM + k0 + kc * 8);
        CP_ASYNC16(sB + off0, Bw + (size_t)rowB0 * KDIM + k0 + kc * 8);
        CP_ASYNC16(sB + off1, Bw + (size_t)rowB1 * KDIM + k0 + kc * 8);
    };

    issue(0, 0); CP_COMMIT();
    issue(1, 1); CP_COMMIT();
    issue(2, 2); CP_COMMIT();

    // ldmatrix lane address pieces
    int lrow = ((lane >> 3) & 1) * 8 + (lane & 7);
    int lkof = ((lane >> 4) & 1) * 8;

    for (int c = 0; c < NC; c++) {
        int slot = c & 3;
        if (c + 3 < NC) { CP_WAIT2(); }
        else            { CP_WAIT0(); }
        __syncthreads();
        if (c + 3 < NC) {
            issue(c + 3, (c + 3) & 3); CP_COMMIT();
        }

        uint32_t sA = sbase + slot * STAGE_B;
        uint32_t sB = sA + TILE_B;

#pragma unroll
        for (int kk = 0; kk < 2; kk++) {
            int k0 = kk * 16;
            // b[g] regs: 0 = n0-7/k0-7, 1 = n8-15/k0-7, 2 = n0-7/k8-15, 3 = n8-15/k8-15
            uint32_t b[4][4];
#pragma unroll
            for (int g = 0; g < 4; g++) {
                uint32_t addr = sB + (uint32_t)((wn * 64 + g * 16 + lrow) * 80
                                                + (k0 + lkof) * 2);
                LDSM4(b[g][0], b[g][1], b[g][2], b[g][3], addr);
            }
            uint32_t a[2][4];
#pragma unroll
            for (int mi = 0; mi < 2; mi++) {
                uint32_t addr = sA + (uint32_t)((wm * 32 + mi * 16 + lrow) * 80
                                                + (k0 + lkof) * 2);
                LDSM4(a[mi][0], a[mi][1], a[mi][2], a[mi][3], addr);
            }
#pragma unroll
            for (int mi = 0; mi < 2; mi++)
#pragma unroll
                for (int ni = 0; ni < 8; ni++) {
                    int gg = ni >> 1, hh = ni & 1;
                    MMA16816(acc[mi][ni], a[mi], b[gg][hh], b[gg][hh + 2]);
                }
        }
    }

    // ---------------- epilogue ----------------
    int colbase = n0 + wn * 64 + (lane & 3) * 2;
    int rbase   = r0 + wm * 32 + (lane >> 2);
    size_t bofs = (size_t)e * NTOT;

#pragma unroll
    for (int mi = 0; mi < 2; mi++) {
#pragma unroll
        for (int half = 0; half < 2; half++) {
            int p = rbase + mi * 16 + half * 8;
            if (p >= row_end) continue;
            if (MODE == 1) {
#pragma unroll
                for (int ni = 0; ni < 8; ni++) {
                    int col = colbase + ni * 8;
                    float v0 = acc[mi][ni][half * 2]     + bias[bofs + col];
                    float v1 = acc[mi][ni][half * 2 + 1] + bias[bofs + col + 1];
                    v0 = gelu_exact(v0);
                    v1 = gelu_exact(v1);
                    uint32_t hw = ((uint32_t)__half_as_ushort(__float2half_rn(v1)) << 16)
                                  | __half_as_ushort(__float2half_rn(v0));
                    *(uint32_t*)(g_h + (size_t)p * H_ + col) = hw;
                }
            } else {
                int tok = g_perm[p];
                float gprob = g_prob[tok];
                float* orow = out + (size_t)tok * C_;
#pragma unroll
                for (int ni = 0; ni < 8; ni++) {
                    int col = colbase + ni * 8;
                    float2 o;
                    o.x = gprob * (acc[mi][ni][half * 2]     + bias[bofs + col]);
                    o.y = gprob * (acc[mi][ni][half * 2 + 1] + bias[bofs + col + 1]);
                    *(float2*)(orow + col) = o;
                }
            }
        }
    }
}

// ---------------- launch ------------------------------------------------------
extern "C" void kernel_launch(void* const* d_in, const int* in_sizes, int n_in,
                              void* d_out, int out_size) {
    const float* x  = (const float*)d_in[0];
    const float* Wr = (const float*)d_in[1];
    const float* br = (const float*)d_in[2];
    const float* W1 = (const float*)d_in[3];
    const float* b1 = (const float*)d_in[4];
    const float* W2 = (const float*)d_in[5];
    const float* b2 = (const float*)d_in[6];
    float* out = (float*)d_out;

    float* aux_ptr = (out_size > NTOK * C_) ? (out + (out_size - 1)) : nullptr;

    cudaFuncSetAttribute(gemm_hmma_kernel<1>,
                         cudaFuncAttributeMaxDynamicSharedMemorySize, GEMM_SMEM);
    cudaFuncSetAttribute(gemm_hmma_kernel<2>,
                         cudaFuncAttributeMaxDynamicSharedMemorySize, GEMM_SMEM);

    zero_counts_kernel<<<1, 32>>>();
    router_kernel<<<NTOK / 8, 256>>>(x, Wr, br);
    offsets_kernel<<<1, 1>>>(aux_ptr);
    permute_kernel<<<NTOK / 256, 256>>>();
    convert_x_kernel<<<NTOK, 256>>>(x);

    dim3 tb(32, 8);
    transpose_kernel<1><<<dim3(H_ / 32, C_ / 32, E_), tb>>>(W1);
    transpose_kernel<2><<<dim3(C_ / 32, H_ / 32, E_), tb>>>(W2);

    gemm_hmma_kernel<1><<<dim3(NTOK / 128, H_ / 128, E_), 256, GEMM_SMEM>>>(b1, nullptr);
    gemm_hmma_kernel<2><<<dim3(NTOK / 128, C_ / 128, E_), 256, GEMM_SMEM>>>(b2, out);
}

// round 9
// speedup vs baseline: 7.9933x; 1.0764x over previous
#include <cuda_runtime.h>
#include <cuda_fp16.h>
#include <math.h>
#include <stdint.h>

#define B_    4
#define T_    2048
#define C_    1024
#define E_    8
#define H_    4096
#define NTOK  (B_ * T_)     // 8192
#define MAXBLK 80           // >= sum ceil(count_e/128) worst case (64+8)

// ---------------- scratch (device globals; no runtime allocation) -----------
__device__ int   g_idx[NTOK];
__device__ float g_prob[NTOK];
__device__ int   g_counts[E_];
__device__ int   g_offsets[E_ + 1];
__device__ int   g_cursor[E_];
__device__ int   g_perm[NTOK];
__device__ int   g_nblk;
__device__ int   g_blk_e[MAXBLK];
__device__ int   g_blk_r0[MAXBLK];

// fp16 operands (single-rounded; fp32 accumulate in MMA). Weights keep native
// layout: W1 [e][C][H], W2 [e][H][C]  (both are [k][n] for their GEMM).
__device__ __half g_xp[(size_t)NTOK * C_];        // permuted x  [p][C]
__device__ __half g_w1[(size_t)E_ * C_ * H_];     // fl16(W1)
__device__ __half g_w2[(size_t)E_ * H_ * C_];     // fl16(W2)
__device__ __half g_h[(size_t)NTOK * H_];         // hidden (permuted rows)

__device__ __forceinline__ float gelu_exact(float v) {
    return 0.5f * v * (1.0f + erff(v * 0.7071067811865476f));
}

__device__ __forceinline__ uint32_t smem_u32(const void* p) {
    uint32_t a;
    asm("{ .reg .u64 t; cvta.to.shared.u64 t, %1; cvt.u32.u64 %0, t; }"
        : "=r"(a) : "l"(p));
    return a;
}

#define LDSM4(R0, R1, R2, R3, addr)                                          \
    asm volatile("ldmatrix.sync.aligned.m8n8.x4.shared.b16 {%0,%1,%2,%3}, [%4];" \
                 : "=r"(R0), "=r"(R1), "=r"(R2), "=r"(R3) : "r"(addr))

#define LDSM4T(R0, R1, R2, R3, addr)                                         \
    asm volatile("ldmatrix.sync.aligned.m8n8.x4.trans.shared.b16 {%0,%1,%2,%3}, [%4];" \
                 : "=r"(R0), "=r"(R1), "=r"(R2), "=r"(R3) : "r"(addr))

#define MMA16816(C, A, B0, B1)                                               \
    asm volatile("mma.sync.aligned.m16n8k16.row.col.f32.f16.f16.f32 "        \
                 "{%0,%1,%2,%3},{%4,%5,%6,%7},{%8,%9},{%0,%1,%2,%3};"        \
                 : "+f"((C)[0]), "+f"((C)[1]), "+f"((C)[2]), "+f"((C)[3])    \
                 : "r"((A)[0]), "r"((A)[1]), "r"((A)[2]), "r"((A)[3]),       \
                   "r"(B0), "r"(B1))

#define CP_ASYNC16(dst, src)                                                 \
    asm volatile("cp.async.cg.shared.global [%0], [%1], 16;" :: "r"(dst), "l"(src))
#define CP_COMMIT()  asm volatile("cp.async.commit_group;" ::: "memory")
#define CP_WAIT2()   asm volatile("cp.async.wait_group 2;" ::: "memory")
#define CP_WAIT0()   asm volatile("cp.async.wait_group 0;" ::: "memory")

// ---------------- 0-3. routing -----------------------------------------------
__global__ void zero_counts_kernel() {
    if (threadIdx.x < E_) g_counts[threadIdx.x] = 0;
}

__global__ __launch_bounds__(256) void router_kernel(
        const float* __restrict__ x, const float* __restrict__ Wr,
        const float* __restrict__ br) {
    int warp = (blockIdx.x * blockDim.x + threadIdx.x) >> 5;
    int lane = threadIdx.x & 31;
    if (warp >= NTOK) return;
    const float* xr = x + (size_t)warp * C_;
    float acc[E_];
#pragma unroll
    for (int e = 0; e < E_; e++) acc[e] = 0.f;
    for (int k = lane; k < C_; k += 32) {
        float xv = xr[k];
        const float* wrow = Wr + k * E_;
#pragma unroll
        for (int e = 0; e < E_; e++) acc[e] += xv * wrow[e];
    }
#pragma unroll
    for (int e = 0; e < E_; e++) {
#pragma unroll
        for (int off = 16; off > 0; off >>= 1)
            acc[e] += __shfl_xor_sync(0xffffffffu, acc[e], off);
    }
    if (lane == 0) {
        float lmax = -1e30f; int best = 0;
#pragma unroll
        for (int e = 0; e < E_; e++) {
            float l = acc[e] + br[e];
            acc[e] = l;
            if (l > lmax) { lmax = l; best = e; }
        }
        float s = 0.f;
#pragma unroll
        for (int e = 0; e < E_; e++) s += expf(acc[e] - lmax);
        g_prob[warp] = 1.0f / s;
        g_idx[warp]  = best;
        atomicAdd(&g_counts[best], 1);
    }
}

__global__ void offsets_kernel(float* aux_out) {
    int off = 0;
    float aux = 0.f;
    int nb = 0;
#pragma unroll
    for (int e = 0; e < E_; e++) {
        g_offsets[e] = off;
        g_cursor[e]  = off;
        int c = g_counts[e];
        // enumerate 128-row blocks for this expert
        for (int r0 = off; r0 < off + c; r0 += 128) {
            g_blk_e[nb]  = e;
            g_blk_r0[nb] = r0;
            nb++;
        }
        off += c;
        float frac = (float)c / (float)NTOK;
        float d = frac - (1.0f / (float)E_);
        aux += d * d;
    }
    g_offsets[E_] = off;
    g_nblk = nb;
    if (aux_out) *aux_out = aux / (float)E_;
}

__global__ void permute_kernel() {
    int t = blockIdx.x * blockDim.x + threadIdx.x;
    if (t >= NTOK) return;
    int e = g_idx[t];
    int pos = atomicAdd(&g_cursor[e], 1);
    g_perm[pos] = t;
}

// ---------------- 4. convert + permute x to fp16 ------------------------------
__global__ __launch_bounds__(256) void convert_x_kernel(const float* __restrict__ x) {
    int p = blockIdx.x;
    int tok = g_perm[p];
    int k = threadIdx.x * 4;
    float4 v = *(const float4*)(x + (size_t)tok * C_ + k);
    uint2 hw;
    hw.x = ((uint32_t)__half_as_ushort(__float2half_rn(v.y)) << 16)
           | __half_as_ushort(__float2half_rn(v.x));
    hw.y = ((uint32_t)__half_as_ushort(__float2half_rn(v.w)) << 16)
           | __half_as_ushort(__float2half_rn(v.z));
    *(uint2*)(g_xp + (size_t)p * C_ + k) = hw;
}

// ---------------- 5. weight convert fp32 -> fp16 (streaming, no transpose) ----
__global__ __launch_bounds__(256) void convert_w_kernel(
        const float4* __restrict__ src, __half* __restrict__ dst) {
    size_t i = (size_t)blockIdx.x * 256 + threadIdx.x;
    float4 v = src[i];
    uint2 hw;
    hw.x = ((uint32_t)__half_as_ushort(__float2half_rn(v.y)) << 16)
           | __half_as_ushort(__float2half_rn(v.x));
    hw.y = ((uint32_t)__half_as_ushort(__float2half_rn(v.w)) << 16)
           | __half_as_ushort(__float2half_rn(v.z));
    *(uint2*)(dst + i * 4) = hw;
}

// ---------------- 6/7. HMMA grouped GEMM (fp16, native-layout B) --------------
// A tile [128 m][32 k] pitch 80B (non-trans LDSM). B tile [32 k][128 n] pitch
// 272B (trans LDSM, conflict-free: 272/16=17, odd). 4-stage cp.async pipeline.
#define A_PITCH  80
#define A_TILE   10240            // 128*80
#define B_PITCH  272
#define B_TILE   8704             // 32*272
#define STAGE_B  (A_TILE + B_TILE)  // 18944
#define GEMM_SMEM (4 * STAGE_B)     // 75776

template<int MODE>
__global__ __launch_bounds__(256, 2) void gemm_hmma_kernel(
        const float* __restrict__ bias, float* __restrict__ out) {
    constexpr int KDIM = (MODE == 1) ? C_ : H_;
    constexpr int NTOT = (MODE == 1) ? H_ : C_;
    constexpr int NC   = KDIM / 32;        // chunks

    extern __shared__ char smem[];
    int bx = blockIdx.x;
    if (bx >= g_nblk) return;
    int e  = g_blk_e[bx];
    int r0 = g_blk_r0[bx];
    int row_end = g_offsets[e + 1];
    int n0 = blockIdx.y * 128;

    int tid  = threadIdx.x;
    int wid  = tid >> 5, lane = tid & 31;
    int wm   = wid & 3;          // warp row  (4 x 32 rows)
    int wn   = wid >> 2;         // warp col  (2 x 64 cols)

    const __half* A  = (MODE == 1) ? g_xp : g_h;
    const __half* Bw = ((MODE == 1) ? g_w1 : g_w2) + (size_t)e * KDIM * NTOT;

    uint32_t sbase = smem_u32(smem);

    // A copy mapping: rows tid>>2 and +64, k-seg tid&3 (16B each)
    int rowA0 = tid >> 2,  kc = tid & 3;
    int rowA1 = rowA0 + 64;
    int pA0 = r0 + rowA0; if (pA0 >= row_end) pA0 = r0;
    int pA1 = r0 + rowA1; if (pA1 >= row_end) pA1 = r0;
    uint32_t offA0 = rowA0 * A_PITCH + kc * 16;
    uint32_t offA1 = rowA1 * A_PITCH + kc * 16;
    // B copy mapping: k-row tid>>3 (0..31), n-seg tid&7 and +8 (16B each)
    int brow = tid >> 3, bseg = tid & 7;
    uint32_t offB0 = brow * B_PITCH + bseg * 16;
    uint32_t offB1 = offB0 + 128;

    float acc[2][8][4];
#pragma unroll
    for (int i = 0; i < 2; i++)
#pragma unroll
        for (int j = 0; j < 8; j++)
#pragma unroll
            for (int q = 0; q < 4; q++) acc[i][j][q] = 0.f;

    auto issue = [&](int chunk, int slot) {
        int k0 = chunk * 32;
        uint32_t sA = sbase + slot * STAGE_B;
        uint32_t sB = sA + A_TILE;
        CP_ASYNC16(sA + offA0, A + (size_t)pA0 * KDIM + k0 + kc * 8);
        CP_ASYNC16(sA + offA1, A + (size_t)pA1 * KDIM + k0 + kc * 8);
        const __half* bsrc = Bw + (size_t)(k0 + brow) * NTOT + n0 + bseg * 8;
        CP_ASYNC16(sB + offB0, bsrc);
        CP_ASYNC16(sB + offB1, bsrc + 64);
    };

    issue(0, 0); CP_COMMIT();
    issue(1, 1); CP_COMMIT();
    issue(2, 2); CP_COMMIT();

    // lane address pieces
    int lrow = ((lane >> 3) & 1) * 8 + (lane & 7);        // A: m-row within 16
    int lkof = ((lane >> 4) & 1) * 8;                     // A: k-offset
    int bkrow = (lane & 7) + ((lane >> 4) & 1) * 8;       // B: k-row within 16
    int bncol = ((lane >> 3) & 1) * 8;                    // B: n-offset within 16

    for (int c = 0; c < NC; c++) {
        int slot = c & 3;
        if (c + 3 < NC) { CP_WAIT2(); }
        else            { CP_WAIT0(); }
        __syncthreads();
        if (c + 3 < NC) {
            issue(c + 3, (c + 3) & 3); CP_COMMIT();
        }

        uint32_t sA = sbase + slot * STAGE_B;
        uint32_t sB = sA + A_TILE;

#pragma unroll
        for (int kk = 0; kk < 2; kk++) {
            int k0 = kk * 16;
            // B fragments via trans ldmatrix on [k][n] tile:
            // reg0=(k0-7,n0-7) reg1=(k0-7,n8-15) reg2=(k8-15,n0-7) reg3=(k8-15,n8-15)
            uint32_t b[4][4];
#pragma unroll
            for (int g = 0; g < 4; g++) {
                uint32_t addr = sB + (uint32_t)((k0 + bkrow) * B_PITCH
                                                + (wn * 64 + g * 16 + bncol) * 2);
                LDSM4T(b[g][0], b[g][1], b[g][2], b[g][3], addr);
            }
            uint32_t a[2][4];
#pragma unroll
            for (int mi = 0; mi < 2; mi++) {
                uint32_t addr = sA + (uint32_t)((wm * 32 + mi * 16 + lrow) * A_PITCH
                                                + (k0 + lkof) * 2);
                LDSM4(a[mi][0], a[mi][1], a[mi][2], a[mi][3], addr);
            }
#pragma unroll
            for (int mi = 0; mi < 2; mi++)
#pragma unroll
                for (int ni = 0; ni < 8; ni++) {
                    int gg = ni >> 1, hh = ni & 1;
                    MMA16816(acc[mi][ni], a[mi], b[gg][hh], b[gg][hh + 2]);
                }
        }
    }

    // ---------------- epilogue ----------------
    int colbase = n0 + wn * 64 + (lane & 3) * 2;
    int rbase   = r0 + wm * 32 + (lane >> 2);
    size_t bofs = (size_t)e * NTOT;

#pragma unroll
    for (int mi = 0; mi < 2; mi++) {
#pragma unroll
        for (int half = 0; half < 2; half++) {
            int p = rbase + mi * 16 + half * 8;
            if (p >= row_end) continue;
            if (MODE == 1) {
#pragma unroll
                for (int ni = 0; ni < 8; ni++) {
                    int col = colbase + ni * 8;
                    float v0 = acc[mi][ni][half * 2]     + bias[bofs + col];
                    float v1 = acc[mi][ni][half * 2 + 1] + bias[bofs + col + 1];
                    v0 = gelu_exact(v0);
                    v1 = gelu_exact(v1);
                    uint32_t hw = ((uint32_t)__half_as_ushort(__float2half_rn(v1)) << 16)
                                  | __half_as_ushort(__float2half_rn(v0));
                    *(uint32_t*)(g_h + (size_t)p * H_ + col) = hw;
                }
            } else {
                int tok = g_perm[p];
                float gprob = g_prob[tok];
                float* orow = out + (size_t)tok * C_;
#pragma unroll
                for (int ni = 0; ni < 8; ni++) {
                    int col = colbase + ni * 8;
                    float2 o;
                    o.x = gprob * (acc[mi][ni][half * 2]     + bias[bofs + col]);
                    o.y = gprob * (acc[mi][ni][half * 2 + 1] + bias[bofs + col + 1]);
                    *(float2*)(orow + col) = o;
                }
            }
        }
    }
}

// ---------------- launch ------------------------------------------------------
extern "C" void kernel_launch(void* const* d_in, const int* in_sizes, int n_in,
                              void* d_out, int out_size) {
    const float* x  = (const float*)d_in[0];
    const float* Wr = (const float*)d_in[1];
    const float* br = (const float*)d_in[2];
    const float* W1 = (const float*)d_in[3];
    const float* b1 = (const float*)d_in[4];
    const float* W2 = (const float*)d_in[5];
    const float* b2 = (const float*)d_in[6];
    float* out = (float*)d_out;

    float* aux_ptr = (out_size > NTOK * C_) ? (out + (out_size - 1)) : nullptr;

    cudaFuncSetAttribute(gemm_hmma_kernel<1>,
                         cudaFuncAttributeMaxDynamicSharedMemorySize, GEMM_SMEM);
    cudaFuncSetAttribute(gemm_hmma_kernel<2>,
                         cudaFuncAttributeMaxDynamicSharedMemorySize, GEMM_SMEM);

    // weight convert can start before routing (independent)
    __half* d_w1h; cudaGetSymbolAddress((void**)&d_w1h, g_w1);
    __half* d_w2h; cudaGetSymbolAddress((void**)&d_w2h, g_w2);
    convert_w_kernel<<<(E_ * C_ * H_) / 4 / 256, 256>>>((const float4*)W1, d_w1h);
    convert_w_kernel<<<(E_ * H_ * C_) / 4 / 256, 256>>>((const float4*)W2, d_w2h);

    zero_counts_kernel<<<1, 32>>>();
    router_kernel<<<NTOK / 8, 256>>>(x, Wr, br);
    offsets_kernel<<<1, 1>>>(aux_ptr);
    permute_kernel<<<NTOK / 256, 256>>>();
    convert_x_kernel<<<NTOK, 256>>>(x);

    gemm_hmma_kernel<1><<<dim3(72, H_ / 128), 256, GEMM_SMEM>>>(b1, nullptr);
    gemm_hmma_kernel<2><<<dim3(72, C_ / 128), 256, GEMM_SMEM>>>(b2, out);
}